// round 1
// baseline (speedup 1.0000x reference)
#include <cuda_runtime.h>
#include <math.h>
#include <stdint.h>

#define BATCH 8192
#define NRSS  12
#define NLED  256
#define NBLK  444   // 148 SMs * 3 CTAs

// ---- folded weights (computed once per launch by fold_kernel) ----
__device__ float g_WcT[32 * 64];  // WcT[j][i] = sum_d qf_w2[i,d]*kp_w2[j,d]
__device__ float g_v[64];         // v[i] = sum_d qf_w2[i,d]*kp_b2[d]
__device__ float g_bc[32];        // bc[j] = sum_d qf_b2[d]*kp_w2[j,d]
__device__ float g_c0[1];         // c0 = qf_b2 . kp_b2

__global__ void fold_kernel(const float* __restrict__ qf_w2, const float* __restrict__ qf_b2,
                            const float* __restrict__ kp_w2, const float* __restrict__ kp_b2) {
    int e = blockIdx.x * blockDim.x + threadIdx.x;
    if (e < 2048) {
        int j = e >> 6;      // 0..31
        int i = e & 63;      // 0..63
        float acc = 0.f;
        #pragma unroll 8
        for (int d = 0; d < 128; d++) acc += qf_w2[i * 128 + d] * kp_w2[j * 128 + d];
        g_WcT[j * 64 + i] = acc;
    }
    if (e < 64) {
        float acc = 0.f;
        #pragma unroll 8
        for (int d = 0; d < 128; d++) acc += qf_w2[e * 128 + d] * kp_b2[d];
        g_v[e] = acc;
    } else if (e < 96) {
        int j = e - 64;
        float acc = 0.f;
        #pragma unroll 8
        for (int d = 0; d < 128; d++) acc += qf_b2[d] * kp_w2[j * 128 + d];
        g_bc[j] = acc;
    } else if (e == 96) {
        float acc = 0.f;
        for (int d = 0; d < 128; d++) acc += qf_b2[d] * kp_b2[d];
        g_c0[0] = acc;
    }
}

// ---- shared memory layout (dynamic) ----
struct SMem {
    // weights, transposed for conflict-free per-thread row access (odd strides)
    float me1T[64 * 129];   // me1T[j*129+i] = me_w1[i,j]   (i<128, j<64)
    float me2T[32 * 65];    // me2T[j*65+i]  = me_w2[i,j]   (i<64,  j<32)
    float qf1T[64 * 33];    // qf1T[j*33+i]  = qf_w1[i,j]   (i<33,  j<64)
    float WcT [32 * 65];    // WcT[j*65+i]                   (i<64,  j<32)
    float ciT [12 * 33];    // ciT[j*33+i]   = ci_w[i,j]    (i<32,  j<12)
    float kp1 [11 * 32];    // row-major, broadcast access, float4
    float Qh  [12 * 32];    // per-iter: cw-scaled reduced query, float4 reads
    float kpb1[32];
    float v[64];
    float bc[32];
    float meb1[64];
    float meb2[32];
    float qfb1[64];
    float ssw[32];
    float cib[12];
    // per-iteration scratch
    float Ls[128];
    float rss[NRSS];
    float mc[32];
    float cw[NRSS];
    float h1m[64];
    float h1q[12 * 64];
    float qc[NRSS];
    float red[12 * 8];
    float bmax[NRSS];
    float binv[NRSS];
    float prev[3];
    float ssb, c0, inv2s2;
};

__device__ __forceinline__ float wredmax(float v) {
    #pragma unroll
    for (int o = 16; o; o >>= 1) v = fmaxf(v, __shfl_xor_sync(0xffffffffu, v, o));
    return v;
}
__device__ __forceinline__ float wredsum(float v) {
    #pragma unroll
    for (int o = 16; o; o >>= 1) v += __shfl_xor_sync(0xffffffffu, v, o);
    return v;
}

__global__ __launch_bounds__(256, 3)
void cah_kernel(const float* __restrict__ rss_t,
                const float* __restrict__ led_f,
                const float* __restrict__ led_p,
                const float* __restrict__ prevp,
                const int*   __restrict__ fmask,
                const float* __restrict__ lstm,
                const float* __restrict__ me_w1, const float* __restrict__ me_b1,
                const float* __restrict__ me_w2, const float* __restrict__ me_b2,
                const float* __restrict__ ci_w,  const float* __restrict__ ci_b,
                const float* __restrict__ qf_w1, const float* __restrict__ qf_b1,
                const float* __restrict__ kp_w1, const float* __restrict__ kp_b1,
                const float* __restrict__ ss_w,  const float* __restrict__ ss_b,
                float* __restrict__ out) {
    extern __shared__ float smraw[];
    SMem& sm = *reinterpret_cast<SMem*>(smraw);
    const int tid = threadIdx.x, lane = tid & 31, wid = tid >> 5;
    const float NEG_INF = __int_as_float(0xff800000);

    // ---- stage weights once per CTA ----
    for (int idx = tid; idx < 128 * 64; idx += 256) { int i = idx >> 6, j = idx & 63; sm.me1T[j * 129 + i] = me_w1[idx]; }
    for (int idx = tid; idx < 64 * 32;  idx += 256) { int i = idx >> 5, j = idx & 31; sm.me2T[j * 65 + i] = me_w2[idx]; }
    for (int idx = tid; idx < 33 * 64;  idx += 256) { int i = idx >> 6, j = idx & 63; sm.qf1T[j * 33 + i] = qf_w1[idx]; }
    for (int idx = tid; idx < 32 * 64;  idx += 256) { int j = idx >> 6, i = idx & 63; sm.WcT[j * 65 + i] = g_WcT[idx]; }
    for (int idx = tid; idx < 32 * 12;  idx += 256) { int i = idx / 12, j = idx - i * 12; sm.ciT[j * 33 + i] = ci_w[idx]; }
    for (int idx = tid; idx < 11 * 32;  idx += 256) sm.kp1[idx] = kp_w1[idx];
    if (tid < 64) { sm.v[tid] = g_v[tid]; sm.meb1[tid] = me_b1[tid]; sm.qfb1[tid] = qf_b1[tid]; }
    if (tid < 32) { sm.bc[tid] = g_bc[tid]; sm.meb2[tid] = me_b2[tid]; sm.kpb1[tid] = kp_b1[tid]; sm.ssw[tid] = ss_w[tid]; }
    if (tid < 12) sm.cib[tid] = ci_b[tid];
    if (tid == 0) { sm.c0 = g_c0[0]; sm.ssb = ss_b[0]; }

    // per-thread mask bits for LED k = tid
    uint32_t mbits = 0;
    #pragma unroll
    for (int q = 0; q < NRSS; q++) mbits |= (fmask[q * NLED + tid] != 0 ? 1u : 0u) << q;
    __syncthreads();

    for (int b = blockIdx.x; b < BATCH; b += gridDim.x) {
        // prefetch this thread's LED inputs (latency hidden under shared phases)
        const float4* lf4 = reinterpret_cast<const float4*>(led_f + ((size_t)b * NLED + tid) * 8);
        float4 f0 = lf4[0], f1 = lf4[1];
        const float* pp = led_p + ((size_t)b * NLED + tid) * 3;
        float px = pp[0], py = pp[1], pz = pp[2];

        if (tid < 128)      sm.Ls[tid] = lstm[(size_t)b * 128 + tid];
        else if (tid < 140) sm.rss[tid - 128] = rss_t[(size_t)b * NRSS + (tid - 128)];
        else if (tid < 143) sm.prev[tid - 140] = prevp[(size_t)b * 3 + (tid - 140)];
        __syncthreads();

        // h1m = relu(Ls @ me_w1 + b1)   [64]
        if (tid < 64) {
            float acc = sm.meb1[tid];
            const float* r = &sm.me1T[tid * 129];
            #pragma unroll 16
            for (int i = 0; i < 128; i++) acc += sm.Ls[i] * r[i];
            sm.h1m[tid] = fmaxf(acc, 0.f);
        }
        __syncthreads();

        // mc = h1m @ me_w2 + b2   [32]
        if (tid < 32) {
            float acc = sm.meb2[tid];
            const float* r = &sm.me2T[tid * 65];
            #pragma unroll 16
            for (int i = 0; i < 64; i++) acc += sm.h1m[i] * r[i];
            sm.mc[tid] = acc;
        }
        __syncthreads();

        // channel weights + sigma
        if (tid < 12) {
            float acc = sm.cib[tid];
            const float* r = &sm.ciT[tid * 33];
            #pragma unroll
            for (int i = 0; i < 32; i++) acc += sm.mc[i] * r[i];
            float c = 1.f / (1.f + __expf(-acc));
            sm.cw[tid] = c;
            out[(size_t)BATCH * NRSS * NLED + (size_t)b * NRSS + tid] = c;
        } else if (tid == 12) {
            float x = sm.ssb;
            #pragma unroll
            for (int i = 0; i < 32; i++) x += sm.mc[i] * sm.ssw[i];
            float sp = fmaxf(x, 0.f) + log1pf(__expf(-fabsf(x)));
            float sg = sp + 0.5f;
            sm.inv2s2 = 0.5f / (sg * sg);
        }
        __syncthreads();

        // h1q[q][64] = relu([rss_q, mc] @ qf_w1 + b1)  (768 entries, 3 per thread)
        #pragma unroll
        for (int p = 0; p < 3; p++) {
            int e = tid + p * 256;
            int q = e >> 6, j = e & 63;
            const float* r = &sm.qf1T[j * 33];
            float acc = sm.qfb1[j] + sm.rss[q] * r[0];
            #pragma unroll
            for (int i = 0; i < 32; i++) acc += sm.mc[i] * r[1 + i];
            sm.h1q[e] = fmaxf(acc, 0.f);
        }
        __syncthreads();

        // Qh[q][32] = cw[q]*(h1q @ Wc + bc) ; qc[q] = cw[q]*(h1q.v + c0)
        {
            int e = tid;  // 0..255 -> Qh entries 0..255
            {
                int q = e >> 5, j = e & 31;
                const float* r  = &sm.WcT[j * 65];
                const float* hq = &sm.h1q[q << 6];
                float acc = sm.bc[j];
                #pragma unroll 16
                for (int i = 0; i < 64; i++) acc += hq[i] * r[i];
                sm.Qh[e] = acc * sm.cw[q];
            }
            int e2 = tid + 256;
            if (e2 < 384) {
                int q = e2 >> 5, j = e2 & 31;
                const float* r  = &sm.WcT[j * 65];
                const float* hq = &sm.h1q[q << 6];
                float acc = sm.bc[j];
                #pragma unroll 16
                for (int i = 0; i < 64; i++) acc += hq[i] * r[i];
                sm.Qh[e2] = acc * sm.cw[q];
            } else if (e2 < 396) {
                int q = e2 - 384;
                const float* hq = &sm.h1q[q << 6];
                float acc = sm.c0;
                #pragma unroll 16
                for (int i = 0; i < 64; i++) acc += hq[i] * sm.v[i];
                sm.qc[q] = acc * sm.cw[q];
            }
        }
        __syncthreads();

        // H row for LED k=tid (registers), then scores s[q] = Qh[q].h + qc[q] - dist/2s^2
        float kin[11] = {f0.x, f0.y, f0.z, f0.w, f1.x, f1.y, f1.z, f1.w, px, py, pz};
        float h[32];
        {
            const float4* bp = (const float4*)sm.kpb1;
            #pragma unroll
            for (int jj = 0; jj < 8; jj++) {
                float4 w = bp[jj];
                h[4 * jj] = w.x; h[4 * jj + 1] = w.y; h[4 * jj + 2] = w.z; h[4 * jj + 3] = w.w;
            }
        }
        #pragma unroll
        for (int i = 0; i < 11; i++) {
            float t = kin[i];
            const float4* wp = (const float4*)&sm.kp1[i * 32];
            #pragma unroll
            for (int jj = 0; jj < 8; jj++) {
                float4 w = wp[jj];
                h[4 * jj]     += t * w.x;
                h[4 * jj + 1] += t * w.y;
                h[4 * jj + 2] += t * w.z;
                h[4 * jj + 3] += t * w.w;
            }
        }
        #pragma unroll
        for (int j = 0; j < 32; j++) h[j] = fmaxf(h[j], 0.f);

        float dx = sm.prev[0] - px, dy = sm.prev[1] - py, dz = sm.prev[2] - pz;
        float db = (dx * dx + dy * dy + dz * dz) * sm.inv2s2;

        float s[NRSS];
        #pragma unroll
        for (int q = 0; q < NRSS; q++) {
            float acc = sm.qc[q];
            const float4* wp = (const float4*)&sm.Qh[q * 32];
            #pragma unroll
            for (int jj = 0; jj < 8; jj++) {
                float4 w = wp[jj];
                acc += w.x * h[4 * jj] + w.y * h[4 * jj + 1] + w.z * h[4 * jj + 2] + w.w * h[4 * jj + 3];
            }
            s[q] = acc - db;
            if (!((mbits >> q) & 1)) s[q] = NEG_INF;
        }

        // softmax over k (256 threads): block max then sum, per q
        #pragma unroll
        for (int q = 0; q < NRSS; q++) {
            float v = wredmax(s[q]);
            if (lane == 0) sm.red[q * 8 + wid] = v;
        }
        __syncthreads();
        if (tid < NRSS) {
            float v = sm.red[tid * 8];
            #pragma unroll
            for (int w = 1; w < 8; w++) v = fmaxf(v, sm.red[tid * 8 + w]);
            sm.bmax[tid] = v;
        }
        __syncthreads();
        #pragma unroll
        for (int q = 0; q < NRSS; q++) {
            float ex = __expf(s[q] - sm.bmax[q]);
            s[q] = ex;  // reuse register: s now holds exp values
            float v = wredsum(ex);
            if (lane == 0) sm.red[q * 8 + wid] = v;
        }
        __syncthreads();
        if (tid < NRSS) {
            float v = 0.f;
            #pragma unroll
            for (int w = 0; w < 8; w++) v += sm.red[tid * 8 + w];
            sm.binv[tid] = 1.f / v;
        }
        __syncthreads();
        #pragma unroll
        for (int q = 0; q < NRSS; q++) {
            out[(((size_t)b * NRSS + q) << 8) + tid] = s[q] * sm.binv[q];
        }
        __syncthreads();  // protect smem scratch before next iteration's loads
    }
}

extern "C" void kernel_launch(void* const* d_in, const int* in_sizes, int n_in,
                              void* d_out, int out_size) {
    (void)in_sizes; (void)n_in; (void)out_size;
    const float* rss_t  = (const float*)d_in[0];
    const float* led_f  = (const float*)d_in[1];
    const float* led_p  = (const float*)d_in[2];
    const float* prevp  = (const float*)d_in[3];
    const int*   fmask  = (const int*)  d_in[4];
    const float* lstm   = (const float*)d_in[5];
    const float* me_w1  = (const float*)d_in[6];
    const float* me_b1  = (const float*)d_in[7];
    const float* me_w2  = (const float*)d_in[8];
    const float* me_b2  = (const float*)d_in[9];
    const float* ci_w   = (const float*)d_in[10];
    const float* ci_b   = (const float*)d_in[11];
    const float* qf_w1  = (const float*)d_in[12];
    const float* qf_b1  = (const float*)d_in[13];
    const float* qf_w2  = (const float*)d_in[14];
    const float* qf_b2  = (const float*)d_in[15];
    const float* kp_w1  = (const float*)d_in[16];
    const float* kp_b1  = (const float*)d_in[17];
    const float* kp_w2  = (const float*)d_in[18];
    const float* kp_b2  = (const float*)d_in[19];
    const float* ss_w   = (const float*)d_in[20];
    const float* ss_b   = (const float*)d_in[21];
    float* out = (float*)d_out;

    static int smem_set = 0;
    if (!smem_set) {
        cudaFuncSetAttribute(cah_kernel, cudaFuncAttributeMaxDynamicSharedMemorySize,
                             (int)sizeof(SMem));
        smem_set = 1;
    }

    fold_kernel<<<8, 256>>>(qf_w2, qf_b2, kp_w2, kp_b2);
    cah_kernel<<<NBLK, 256, sizeof(SMem)>>>(rss_t, led_f, led_p, prevp, fmask, lstm,
                                            me_w1, me_b1, me_w2, me_b2, ci_w, ci_b,
                                            qf_w1, qf_b1, kp_w1, kp_b1, ss_w, ss_b, out);
}

// round 2
// speedup vs baseline: 1.0904x; 1.0904x over previous
#include <cuda_runtime.h>
#include <math.h>
#include <stdint.h>

#define BATCH 8192
#define NRSS  12
#define NLED  256
#define NBLK  444   // 148 SMs * 3 CTAs

// ---- folded weights (computed once per launch by fold_kernel) ----
__device__ float g_WcT[32 * 64];  // WcT[j][i] = sum_d qf_w2[i,d]*kp_w2[j,d]
__device__ float g_v[64];         // v[i] = sum_d qf_w2[i,d]*kp_b2[d]
__device__ float g_bc[32];        // bc[j] = sum_d qf_b2[d]*kp_w2[j,d]
__device__ float g_c0[1];         // c0 = qf_b2 . kp_b2

__global__ void fold_kernel(const float* __restrict__ qf_w2, const float* __restrict__ qf_b2,
                            const float* __restrict__ kp_w2, const float* __restrict__ kp_b2) {
    int e = blockIdx.x * blockDim.x + threadIdx.x;
    if (e < 2048) {
        int j = e >> 6;      // 0..31
        int i = e & 63;      // 0..63
        float acc = 0.f;
        #pragma unroll 8
        for (int d = 0; d < 128; d++) acc += qf_w2[i * 128 + d] * kp_w2[j * 128 + d];
        g_WcT[j * 64 + i] = acc;
    }
    if (e < 64) {
        float acc = 0.f;
        #pragma unroll 8
        for (int d = 0; d < 128; d++) acc += qf_w2[e * 128 + d] * kp_b2[d];
        g_v[e] = acc;
    } else if (e < 96) {
        int j = e - 64;
        float acc = 0.f;
        #pragma unroll 8
        for (int d = 0; d < 128; d++) acc += qf_b2[d] * kp_w2[j * 128 + d];
        g_bc[j] = acc;
    } else if (e == 96) {
        float acc = 0.f;
        for (int d = 0; d < 128; d++) acc += qf_b2[d] * kp_b2[d];
        g_c0[0] = acc;
    }
}

// ---- shared memory layout (dynamic) ----
// All float4-read arrays: sizes multiple of 4 floats; row strides odd in float4
// units (33, 17, 9, 17) -> lane bank stride 4 mod 32 -> conflict-free LDS.128.
struct SMem {
    float me1T[64 * 132];   // me1T[j*132+i] = me_w1[i,j]  (i<128, j<64), f4 stride 33
    float me2T[32 * 68];    // me2T[j*68+i]  = me_w2[i,j]  (i<64,  j<32), f4 stride 17
    float qf1mc[64 * 36];   // qf1mc[j*36+i] = qf_w1[1+i,j] (i<32, j<64), f4 stride 9
    float WcT [32 * 68];    // WcT[j*68+i]                  (i<64, j<32), f4 stride 17
    float h1q [12 * 68];    // per-iter scratch, row stride 17 f4 (kills qc conflict)
    float ciT [12 * 33];    // ciT[j*33+i] = ci_w[i,j], scalar reads, stride 33
    float kp1 [11 * 32];    // row-major, broadcast f4
    float Qh  [12 * 32];    // per-iter: cw-scaled reduced query, broadcast f4
    float qf1w0[64];        // qf_w1[0,j]
    float kpb1[32];
    float v[64];
    float bc[32];
    float meb1[64];
    float meb2[32];
    float qfb1[64];
    float ssw[32];
    float Ls[128];
    float mc[32];
    float h1m[64];
    float red[96];
    float cib[12];
    float rss[NRSS];
    float cw[NRSS];
    float qc[NRSS];
    float bmax[NRSS];
    float binv[NRSS];
    float prev[3];
    float ssb, c0, inv2s2;
};

__device__ __forceinline__ float wredmax(float v) {
    #pragma unroll
    for (int o = 16; o; o >>= 1) v = fmaxf(v, __shfl_xor_sync(0xffffffffu, v, o));
    return v;
}
__device__ __forceinline__ float wredsum(float v) {
    #pragma unroll
    for (int o = 16; o; o >>= 1) v += __shfl_xor_sync(0xffffffffu, v, o);
    return v;
}
__device__ __forceinline__ float dot4(float4 a, float4 b) {
    return a.x * b.x + a.y * b.y + a.z * b.z + a.w * b.w;
}

__global__ __launch_bounds__(256, 3)
void cah_kernel(const float* __restrict__ rss_t,
                const float* __restrict__ led_f,
                const float* __restrict__ led_p,
                const float* __restrict__ prevp,
                const int*   __restrict__ fmask,
                const float* __restrict__ lstm,
                const float* __restrict__ me_w1, const float* __restrict__ me_b1,
                const float* __restrict__ me_w2, const float* __restrict__ me_b2,
                const float* __restrict__ ci_w,  const float* __restrict__ ci_b,
                const float* __restrict__ qf_w1, const float* __restrict__ qf_b1,
                const float* __restrict__ kp_w1, const float* __restrict__ kp_b1,
                const float* __restrict__ ss_w,  const float* __restrict__ ss_b,
                float* __restrict__ out) {
    extern __shared__ float smraw[];
    SMem& sm = *reinterpret_cast<SMem*>(smraw);
    const int tid = threadIdx.x, lane = tid & 31, wid = tid >> 5;
    const float NEG_INF = __int_as_float(0xff800000);

    // ---- stage weights once per CTA ----
    for (int idx = tid; idx < 128 * 64; idx += 256) { int i = idx >> 6, j = idx & 63; sm.me1T[j * 132 + i] = me_w1[idx]; }
    for (int idx = tid; idx < 64 * 32;  idx += 256) { int i = idx >> 5, j = idx & 31; sm.me2T[j * 68 + i] = me_w2[idx]; }
    for (int idx = tid; idx < 33 * 64;  idx += 256) {
        int i = idx >> 6, j = idx & 63;
        if (i == 0) sm.qf1w0[j] = qf_w1[idx];
        else        sm.qf1mc[j * 36 + (i - 1)] = qf_w1[idx];
    }
    for (int idx = tid; idx < 32 * 64;  idx += 256) { int j = idx >> 6, i = idx & 63; sm.WcT[j * 68 + i] = g_WcT[idx]; }
    for (int idx = tid; idx < 32 * 12;  idx += 256) { int i = idx / 12, j = idx - i * 12; sm.ciT[j * 33 + i] = ci_w[idx]; }
    for (int idx = tid; idx < 11 * 32;  idx += 256) sm.kp1[idx] = kp_w1[idx];
    if (tid < 64) { sm.v[tid] = g_v[tid]; sm.meb1[tid] = me_b1[tid]; sm.qfb1[tid] = qf_b1[tid]; }
    if (tid < 32) { sm.bc[tid] = g_bc[tid]; sm.meb2[tid] = me_b2[tid]; sm.kpb1[tid] = kp_b1[tid]; sm.ssw[tid] = ss_w[tid]; }
    if (tid < 12) sm.cib[tid] = ci_b[tid];
    if (tid == 0) { sm.c0 = g_c0[0]; sm.ssb = ss_b[0]; }

    // per-thread mask bits for LED k = tid
    uint32_t mbits = 0;
    #pragma unroll
    for (int q = 0; q < NRSS; q++) mbits |= (fmask[q * NLED + tid] != 0 ? 1u : 0u) << q;
    __syncthreads();

    const float4* Ls4  = reinterpret_cast<const float4*>(sm.Ls);
    const float4* mc4  = reinterpret_cast<const float4*>(sm.mc);
    const float4* h1m4 = reinterpret_cast<const float4*>(sm.h1m);
    const float4* v4   = reinterpret_cast<const float4*>(sm.v);

    for (int b = blockIdx.x; b < BATCH; b += gridDim.x) {
        // prefetch this thread's LED inputs (latency hidden under shared phases)
        const float4* lf4 = reinterpret_cast<const float4*>(led_f + ((size_t)b * NLED + tid) * 8);
        float4 f0 = lf4[0], f1 = lf4[1];
        const float* pp = led_p + ((size_t)b * NLED + tid) * 3;
        float px = pp[0], py = pp[1], pz = pp[2];

        if (tid < 32) {
            reinterpret_cast<float4*>(sm.Ls)[tid] =
                reinterpret_cast<const float4*>(lstm + (size_t)b * 128)[tid];
        } else if (tid < 44) sm.rss[tid - 32] = rss_t[(size_t)b * NRSS + (tid - 32)];
        else if (tid < 47)  sm.prev[tid - 44] = prevp[(size_t)b * 3 + (tid - 44)];
        __syncthreads();

        // h1m = relu(Ls @ me_w1 + b1)   [64]  -- float4 inner
        if (tid < 64) {
            float acc = sm.meb1[tid];
            const float4* r = reinterpret_cast<const float4*>(&sm.me1T[tid * 132]);
            #pragma unroll
            for (int i = 0; i < 32; i++) acc += dot4(Ls4[i], r[i]);
            sm.h1m[tid] = fmaxf(acc, 0.f);
        }
        __syncthreads();

        // mc = h1m @ me_w2 + b2   [32]  -- float4 inner
        if (tid < 32) {
            float acc = sm.meb2[tid];
            const float4* r = reinterpret_cast<const float4*>(&sm.me2T[tid * 68]);
            #pragma unroll
            for (int i = 0; i < 16; i++) acc += dot4(h1m4[i], r[i]);
            sm.mc[tid] = acc;
        }
        __syncthreads();

        // channel weights + sigma (tiny), overlapped with h1q (all 256 threads)
        if (tid < 12) {
            float acc = sm.cib[tid];
            const float* r = &sm.ciT[tid * 33];
            #pragma unroll
            for (int i = 0; i < 32; i++) acc += sm.mc[i] * r[i];
            float c = 1.f / (1.f + __expf(-acc));
            sm.cw[tid] = c;
            out[(size_t)BATCH * NRSS * NLED + (size_t)b * NRSS + tid] = c;
        } else if (tid == 12) {
            float x = sm.ssb;
            #pragma unroll
            for (int i = 0; i < 32; i++) x += sm.mc[i] * sm.ssw[i];
            float sp = fmaxf(x, 0.f) + log1pf(__expf(-fabsf(x)));
            float sg = sp + 0.5f;
            sm.inv2s2 = 0.5f / (sg * sg);
        }

        // h1q[q][64] = relu([rss_q, mc] @ qf_w1 + b1)  (768 entries, 3 per thread)
        #pragma unroll
        for (int p = 0; p < 3; p++) {
            int e = tid + p * 256;
            int q = e >> 6, j = e & 63;
            const float4* r = reinterpret_cast<const float4*>(&sm.qf1mc[j * 36]);
            float acc = sm.qfb1[j] + sm.rss[q] * sm.qf1w0[j];
            #pragma unroll
            for (int i = 0; i < 8; i++) acc += dot4(mc4[i], r[i]);
            sm.h1q[q * 68 + j] = fmaxf(acc, 0.f);
        }
        __syncthreads();

        // Qh[q][32] = cw[q]*(h1q @ Wc + bc) ; qc[q] = cw[q]*(h1q.v + c0)
        {
            {   // entries 0..255: q 0..7
                int q = tid >> 5, j = tid & 31;
                const float4* r  = reinterpret_cast<const float4*>(&sm.WcT[j * 68]);
                const float4* hq = reinterpret_cast<const float4*>(&sm.h1q[q * 68]);
                float acc = sm.bc[j];
                #pragma unroll
                for (int i = 0; i < 16; i++) acc += dot4(hq[i], r[i]);
                sm.Qh[(q << 5) + j] = acc * sm.cw[q];
            }
            int e2 = tid + 256;
            if (e2 < 384) {  // q 8..11
                int q = e2 >> 5, j = e2 & 31;
                const float4* r  = reinterpret_cast<const float4*>(&sm.WcT[j * 68]);
                const float4* hq = reinterpret_cast<const float4*>(&sm.h1q[q * 68]);
                float acc = sm.bc[j];
                #pragma unroll
                for (int i = 0; i < 16; i++) acc += dot4(hq[i], r[i]);
                sm.Qh[(q << 5) + j] = acc * sm.cw[q];
            } else if (e2 < 396) {  // qc for q = 0..11, tid 128..139
                int q = e2 - 384;
                const float4* hq = reinterpret_cast<const float4*>(&sm.h1q[q * 68]);
                float acc = sm.c0;
                #pragma unroll
                for (int i = 0; i < 16; i++) acc += dot4(hq[i], v4[i]);
                sm.qc[q] = acc * sm.cw[q];
            }
        }
        __syncthreads();

        // H row for LED k=tid (registers), then scores s[q] = Qh[q].h + qc[q] - dist/2s^2
        float kin[11] = {f0.x, f0.y, f0.z, f0.w, f1.x, f1.y, f1.z, f1.w, px, py, pz};
        float h[32];
        {
            const float4* bp = (const float4*)sm.kpb1;
            #pragma unroll
            for (int jj = 0; jj < 8; jj++) {
                float4 w = bp[jj];
                h[4 * jj] = w.x; h[4 * jj + 1] = w.y; h[4 * jj + 2] = w.z; h[4 * jj + 3] = w.w;
            }
        }
        #pragma unroll
        for (int i = 0; i < 11; i++) {
            float t = kin[i];
            const float4* wp = (const float4*)&sm.kp1[i * 32];
            #pragma unroll
            for (int jj = 0; jj < 8; jj++) {
                float4 w = wp[jj];
                h[4 * jj]     += t * w.x;
                h[4 * jj + 1] += t * w.y;
                h[4 * jj + 2] += t * w.z;
                h[4 * jj + 3] += t * w.w;
            }
        }
        #pragma unroll
        for (int j = 0; j < 32; j++) h[j] = fmaxf(h[j], 0.f);

        float dx = sm.prev[0] - px, dy = sm.prev[1] - py, dz = sm.prev[2] - pz;
        float db = (dx * dx + dy * dy + dz * dz) * sm.inv2s2;

        float s[NRSS];
        #pragma unroll
        for (int q = 0; q < NRSS; q++) {
            float acc = sm.qc[q];
            const float4* wp = (const float4*)&sm.Qh[q * 32];
            #pragma unroll
            for (int jj = 0; jj < 8; jj++) {
                float4 w = wp[jj];
                acc += w.x * h[4 * jj] + w.y * h[4 * jj + 1] + w.z * h[4 * jj + 2] + w.w * h[4 * jj + 3];
            }
            s[q] = acc - db;
            if (!((mbits >> q) & 1)) s[q] = NEG_INF;
        }

        // softmax over k (256 threads): block max then sum, per q
        #pragma unroll
        for (int q = 0; q < NRSS; q++) {
            float v = wredmax(s[q]);
            if (lane == 0) sm.red[q * 8 + wid] = v;
        }
        __syncthreads();
        if (tid < NRSS) {
            float v = sm.red[tid * 8];
            #pragma unroll
            for (int w = 1; w < 8; w++) v = fmaxf(v, sm.red[tid * 8 + w]);
            sm.bmax[tid] = v;
        }
        __syncthreads();
        #pragma unroll
        for (int q = 0; q < NRSS; q++) {
            float ex = __expf(s[q] - sm.bmax[q]);
            s[q] = ex;  // reuse register: s now holds exp values
            float v = wredsum(ex);
            if (lane == 0) sm.red[q * 8 + wid] = v;
        }
        __syncthreads();
        if (tid < NRSS) {
            float v = 0.f;
            #pragma unroll
            for (int w = 0; w < 8; w++) v += sm.red[tid * 8 + w];
            sm.binv[tid] = 1.f / v;
        }
        __syncthreads();
        #pragma unroll
        for (int q = 0; q < NRSS; q++) {
            out[(((size_t)b * NRSS + q) << 8) + tid] = s[q] * sm.binv[q];
        }
        __syncthreads();  // protect smem scratch before next iteration's loads
    }
}

extern "C" void kernel_launch(void* const* d_in, const int* in_sizes, int n_in,
                              void* d_out, int out_size) {
    (void)in_sizes; (void)n_in; (void)out_size;
    const float* rss_t  = (const float*)d_in[0];
    const float* led_f  = (const float*)d_in[1];
    const float* led_p  = (const float*)d_in[2];
    const float* prevp  = (const float*)d_in[3];
    const int*   fmask  = (const int*)  d_in[4];
    const float* lstm   = (const float*)d_in[5];
    const float* me_w1  = (const float*)d_in[6];
    const float* me_b1  = (const float*)d_in[7];
    const float* me_w2  = (const float*)d_in[8];
    const float* me_b2  = (const float*)d_in[9];
    const float* ci_w   = (const float*)d_in[10];
    const float* ci_b   = (const float*)d_in[11];
    const float* qf_w1  = (const float*)d_in[12];
    const float* qf_b1  = (const float*)d_in[13];
    const float* qf_w2  = (const float*)d_in[14];
    const float* qf_b2  = (const float*)d_in[15];
    const float* kp_w1  = (const float*)d_in[16];
    const float* kp_b1  = (const float*)d_in[17];
    const float* kp_w2  = (const float*)d_in[18];
    const float* kp_b2  = (const float*)d_in[19];
    const float* ss_w   = (const float*)d_in[20];
    const float* ss_b   = (const float*)d_in[21];
    float* out = (float*)d_out;

    static int smem_set = 0;
    if (!smem_set) {
        cudaFuncSetAttribute(cah_kernel, cudaFuncAttributeMaxDynamicSharedMemorySize,
                             (int)sizeof(SMem));
        smem_set = 1;
    }

    fold_kernel<<<8, 256>>>(qf_w2, qf_b2, kp_w2, kp_b2);
    cah_kernel<<<NBLK, 256, sizeof(SMem)>>>(rss_t, led_f, led_p, prevp, fmask, lstm,
                                            me_w1, me_b1, me_w2, me_b2, ci_w, ci_b,
                                            qf_w1, qf_b1, kp_w1, kp_b1, ss_w, ss_b, out);
}

// round 5
// speedup vs baseline: 1.2180x; 1.1171x over previous
#include <cuda_runtime.h>
#include <math.h>
#include <stdint.h>

#define BATCH 8192
#define NRSS  12
#define NLED  256
#define NBLK  444   // 148 SMs * 3 CTAs
#define NT    128   // threads per CTA; each thread owns 2 LEDs

// ---- folded weights (computed once per launch by fold_kernel) ----
__device__ float g_WcT[32 * 64];  // WcT[j][i] = sum_d qf_w2[i,d]*kp_w2[j,d]
__device__ float g_v[64];         // v[i] = sum_d qf_w2[i,d]*kp_b2[d]
__device__ float g_bc[32];        // bc[j] = sum_d qf_b2[d]*kp_w2[j,d]
__device__ float g_c0[1];         // c0 = qf_b2 . kp_b2

__global__ void fold_kernel(const float* __restrict__ qf_w2, const float* __restrict__ qf_b2,
                            const float* __restrict__ kp_w2, const float* __restrict__ kp_b2) {
    int e = blockIdx.x * blockDim.x + threadIdx.x;
    if (e < 2048) {
        int j = e >> 6, i = e & 63;
        float acc = 0.f;
        #pragma unroll 8
        for (int d = 0; d < 128; d++) acc += qf_w2[i * 128 + d] * kp_w2[j * 128 + d];
        g_WcT[j * 64 + i] = acc;
    }
    if (e < 64) {
        float acc = 0.f;
        #pragma unroll 8
        for (int d = 0; d < 128; d++) acc += qf_w2[e * 128 + d] * kp_b2[d];
        g_v[e] = acc;
    } else if (e < 96) {
        int j = e - 64;
        float acc = 0.f;
        #pragma unroll 8
        for (int d = 0; d < 128; d++) acc += qf_b2[d] * kp_w2[j * 128 + d];
        g_bc[j] = acc;
    } else if (e == 96) {
        float acc = 0.f;
        for (int d = 0; d < 128; d++) acc += qf_b2[d] * kp_b2[d];
        g_c0[0] = acc;
    }
}

// ---- shared memory layout (dynamic) ----
struct SMem {
    float me1T[64 * 132];   // me1T[j*132+i] = me_w1[i,j]
    float me2T[32 * 68];    // me2T[j*68+i]  = me_w2[i,j]
    float qf1mc[64 * 36];   // qf1mc[j*36+i] = qf_w1[1+i,j]
    float WcT [32 * 68];
    float h1q [12 * 68];
    float ciT [12 * 33];
    float kp1 [11 * 32];
    float Qh  [12 * 32];
    float qf1w0[64];
    float kpb1[32];
    float v[64];
    float bc[32];
    float meb1[64];
    float meb2[32];
    float qfb1[64];
    float ssw[32];
    float Ls[128];
    float mc[32];
    float h1m[64];
    float red[48];
    float cib[12];
    float rss[NRSS];
    float cw[NRSS];
    float qc[NRSS];
    float bmax[NRSS];
    float binv[NRSS];
    float prev[3];
    float ssb, c0, inv2s2;
};

__device__ __forceinline__ float wredmax(float v) {
    #pragma unroll
    for (int o = 16; o; o >>= 1) v = fmaxf(v, __shfl_xor_sync(0xffffffffu, v, o));
    return v;
}
__device__ __forceinline__ float wredsum(float v) {
    #pragma unroll
    for (int o = 16; o; o >>= 1) v += __shfl_xor_sync(0xffffffffu, v, o);
    return v;
}
__device__ __forceinline__ float dot4(float4 a, float4 b) {
    return a.x * b.x + a.y * b.y + a.z * b.z + a.w * b.w;
}

__global__ __launch_bounds__(NT, 3)
void cah_kernel(const float* __restrict__ rss_t,
                const float* __restrict__ led_f,
                const float* __restrict__ led_p,
                const float* __restrict__ prevp,
                const int*   __restrict__ fmask,
                const float* __restrict__ lstm,
                const float* __restrict__ me_w1, const float* __restrict__ me_b1,
                const float* __restrict__ me_w2, const float* __restrict__ me_b2,
                const float* __restrict__ ci_w,  const float* __restrict__ ci_b,
                const float* __restrict__ qf_w1, const float* __restrict__ qf_b1,
                const float* __restrict__ kp_w1, const float* __restrict__ kp_b1,
                const float* __restrict__ ss_w,  const float* __restrict__ ss_b,
                float* __restrict__ out) {
    extern __shared__ float smraw[];
    SMem& sm = *reinterpret_cast<SMem*>(smraw);
    const int tid = threadIdx.x, lane = tid & 31, wid = tid >> 5;
    const float NEG_INF = __int_as_float(0xff800000);

    // ---- stage weights once per CTA ----
    for (int idx = tid; idx < 128 * 64; idx += NT) { int i = idx >> 6, j = idx & 63; sm.me1T[j * 132 + i] = me_w1[idx]; }
    for (int idx = tid; idx < 64 * 32;  idx += NT) { int i = idx >> 5, j = idx & 31; sm.me2T[j * 68 + i] = me_w2[idx]; }
    for (int idx = tid; idx < 33 * 64;  idx += NT) {
        int i = idx >> 6, j = idx & 63;
        if (i == 0) sm.qf1w0[j] = qf_w1[idx];
        else        sm.qf1mc[j * 36 + (i - 1)] = qf_w1[idx];
    }
    for (int idx = tid; idx < 32 * 64;  idx += NT) { int j = idx >> 6, i = idx & 63; sm.WcT[j * 68 + i] = g_WcT[idx]; }
    for (int idx = tid; idx < 32 * 12;  idx += NT) { int i = idx / 12, j = idx - i * 12; sm.ciT[j * 33 + i] = ci_w[idx]; }
    for (int idx = tid; idx < 11 * 32;  idx += NT) sm.kp1[idx] = kp_w1[idx];
    if (tid < 64) { sm.v[tid] = g_v[tid]; sm.meb1[tid] = me_b1[tid]; sm.qfb1[tid] = qf_b1[tid]; }
    if (tid < 32) { sm.bc[tid] = g_bc[tid]; sm.meb2[tid] = me_b2[tid]; sm.kpb1[tid] = kp_b1[tid]; sm.ssw[tid] = ss_w[tid]; }
    if (tid < 12) sm.cib[tid] = ci_b[tid];
    if (tid == 0) { sm.c0 = g_c0[0]; sm.ssb = ss_b[0]; }

    // per-thread mask bits for LEDs ka=tid, kb=tid+128
    uint32_t mba = 0, mbb = 0;
    #pragma unroll
    for (int q = 0; q < NRSS; q++) {
        mba |= (fmask[q * NLED + tid] != 0 ? 1u : 0u) << q;
        mbb |= (fmask[q * NLED + tid + 128] != 0 ? 1u : 0u) << q;
    }
    __syncthreads();

    const float4* Ls4  = reinterpret_cast<const float4*>(sm.Ls);
    const float4* h1m4 = reinterpret_cast<const float4*>(sm.h1m);

    for (int b = blockIdx.x; b < BATCH; b += gridDim.x) {
        // prefetch this thread's 2 LEDs (latency hidden under shared phases)
        const float4* lfa = reinterpret_cast<const float4*>(led_f + ((size_t)b * NLED + tid) * 8);
        const float4* lfb = reinterpret_cast<const float4*>(led_f + ((size_t)b * NLED + tid + 128) * 8);
        float4 fa0 = lfa[0], fa1 = lfa[1];
        float4 fb0 = lfb[0], fb1 = lfb[1];
        const float* ppa = led_p + ((size_t)b * NLED + tid) * 3;
        const float* ppb = led_p + ((size_t)b * NLED + tid + 128) * 3;
        float pax = ppa[0], pay = ppa[1], paz = ppa[2];
        float pbx = ppb[0], pby = ppb[1], pbz = ppb[2];

        if (tid < 32) {
            reinterpret_cast<float4*>(sm.Ls)[tid] =
                reinterpret_cast<const float4*>(lstm + (size_t)b * 128)[tid];
        } else if (tid < 44) sm.rss[tid - 32] = rss_t[(size_t)b * NRSS + (tid - 32)];
        else if (tid < 47)  sm.prev[tid - 44] = prevp[(size_t)b * 3 + (tid - 44)];
        __syncthreads();

        // h1m = relu(Ls @ me_w1 + b1)  [64], 2 accumulators to break the chain
        if (tid < 64) {
            float a0 = sm.meb1[tid], a1 = 0.f;
            const float4* r = reinterpret_cast<const float4*>(&sm.me1T[tid * 132]);
            #pragma unroll
            for (int i = 0; i < 32; i += 2) { a0 += dot4(Ls4[i], r[i]); a1 += dot4(Ls4[i + 1], r[i + 1]); }
            sm.h1m[tid] = fmaxf(a0 + a1, 0.f);
        }
        __syncthreads();

        // mc = h1m @ me_w2 + b2   [32]
        if (tid < 32) {
            float a0 = sm.meb2[tid], a1 = 0.f;
            const float4* r = reinterpret_cast<const float4*>(&sm.me2T[tid * 68]);
            #pragma unroll
            for (int i = 0; i < 16; i += 2) { a0 += dot4(h1m4[i], r[i]); a1 += dot4(h1m4[i + 1], r[i + 1]); }
            sm.mc[tid] = a0 + a1;
        }
        __syncthreads();

        // channel weights + sigma (tid<13), overlapped with h1q (all threads)
        if (tid < 12) {
            float acc = sm.cib[tid];
            const float* r = &sm.ciT[tid * 33];
            #pragma unroll
            for (int i = 0; i < 32; i++) acc += sm.mc[i] * r[i];
            float c = 1.f / (1.f + __expf(-acc));
            sm.cw[tid] = c;
            out[(size_t)BATCH * NRSS * NLED + (size_t)b * NRSS + tid] = c;
        } else if (tid == 12) {
            float x = sm.ssb;
            #pragma unroll
            for (int i = 0; i < 32; i++) x += sm.mc[i] * sm.ssw[i];
            float sp = fmaxf(x, 0.f) + log1pf(__expf(-fabsf(x)));
            float sg = sp + 0.5f;
            sm.inv2s2 = 0.5f / (sg * sg);
        }

        // h1q: thread handles fixed j = tid&63, q in {2p + (tid>>6)}, p=0..5.
        // Weight row + mc cached in registers -> 16 LDS.128 total per thread.
        {
            int j = tid & 63, hi = tid >> 6;
            float4 wr[8], mcr[8];
            const float4* r = reinterpret_cast<const float4*>(&sm.qf1mc[j * 36]);
            const float4* m4 = reinterpret_cast<const float4*>(sm.mc);
            #pragma unroll
            for (int i = 0; i < 8; i++) { wr[i] = r[i]; mcr[i] = m4[i]; }
            float w0 = sm.qf1w0[j], bj = sm.qfb1[j];
            #pragma unroll
            for (int p = 0; p < 6; p++) {
                int q = 2 * p + hi;
                float a0 = bj + sm.rss[q] * w0, a1 = 0.f;
                #pragma unroll
                for (int i = 0; i < 8; i += 2) { a0 += dot4(mcr[i], wr[i]); a1 += dot4(mcr[i + 1], wr[i + 1]); }
                sm.h1q[q * 68 + j] = fmaxf(a0 + a1, 0.f);
            }
        }
        __syncthreads();

        // Qh[q][32] = cw[q]*(h1q @ Wc + bc); WcT row cached, q in {4p + (tid>>5)}
        {
            int j = tid & 31, qo = tid >> 5;
            float4 wr[16];
            const float4* r = reinterpret_cast<const float4*>(&sm.WcT[j * 68]);
            #pragma unroll
            for (int i = 0; i < 16; i++) wr[i] = r[i];
            float bj = sm.bc[j];
            #pragma unroll
            for (int p = 0; p < 3; p++) {
                int q = 4 * p + qo;
                const float4* hq = reinterpret_cast<const float4*>(&sm.h1q[q * 68]);
                float a0 = bj, a1 = 0.f;
                #pragma unroll
                for (int i = 0; i < 16; i += 2) { a0 += dot4(hq[i], wr[i]); a1 += dot4(hq[i + 1], wr[i + 1]); }
                sm.Qh[(q << 5) + j] = (a0 + a1) * sm.cw[q];
            }
            if (tid < 12) {  // qc[q]
                const float4* hq = reinterpret_cast<const float4*>(&sm.h1q[tid * 68]);
                const float4* v4 = reinterpret_cast<const float4*>(sm.v);
                float a0 = sm.c0, a1 = 0.f;
                #pragma unroll
                for (int i = 0; i < 16; i += 2) { a0 += dot4(hq[i], v4[i]); a1 += dot4(hq[i + 1], v4[i + 1]); }
                sm.qc[tid] = (a0 + a1) * sm.cw[tid];
            }
        }
        __syncthreads();

        // H rows for both LEDs; every broadcast load feeds 2 FMAs (a and b)
        float kina[11] = {fa0.x, fa0.y, fa0.z, fa0.w, fa1.x, fa1.y, fa1.z, fa1.w, pax, pay, paz};
        float kinb[11] = {fb0.x, fb0.y, fb0.z, fb0.w, fb1.x, fb1.y, fb1.z, fb1.w, pbx, pby, pbz};
        float ha[32], hb[32];
        {
            const float4* bp = (const float4*)sm.kpb1;
            #pragma unroll
            for (int jj = 0; jj < 8; jj++) {
                float4 w = bp[jj];
                ha[4 * jj] = w.x; ha[4 * jj + 1] = w.y; ha[4 * jj + 2] = w.z; ha[4 * jj + 3] = w.w;
                hb[4 * jj] = w.x; hb[4 * jj + 1] = w.y; hb[4 * jj + 2] = w.z; hb[4 * jj + 3] = w.w;
            }
        }
        #pragma unroll
        for (int i = 0; i < 11; i++) {
            float ta = kina[i], tb = kinb[i];
            const float4* wp = (const float4*)&sm.kp1[i * 32];
            #pragma unroll
            for (int jj = 0; jj < 8; jj++) {
                float4 w = wp[jj];
                ha[4 * jj]     += ta * w.x; hb[4 * jj]     += tb * w.x;
                ha[4 * jj + 1] += ta * w.y; hb[4 * jj + 1] += tb * w.y;
                ha[4 * jj + 2] += ta * w.z; hb[4 * jj + 2] += tb * w.z;
                ha[4 * jj + 3] += ta * w.w; hb[4 * jj + 3] += tb * w.w;
            }
        }
        #pragma unroll
        for (int j = 0; j < 32; j++) { ha[j] = fmaxf(ha[j], 0.f); hb[j] = fmaxf(hb[j], 0.f); }

        float dax = sm.prev[0] - pax, day = sm.prev[1] - pay, daz = sm.prev[2] - paz;
        float dbx = sm.prev[0] - pbx, dby = sm.prev[1] - pby, dbz = sm.prev[2] - pbz;
        float dba = (dax * dax + day * day + daz * daz) * sm.inv2s2;
        float dbb = (dbx * dbx + dby * dby + dbz * dbz) * sm.inv2s2;

        float sa[NRSS], sb[NRSS];
        #pragma unroll
        for (int q = 0; q < NRSS; q++) {
            float aa = sm.qc[q], ab = aa;
            const float4* wp = (const float4*)&sm.Qh[q * 32];
            #pragma unroll
            for (int jj = 0; jj < 8; jj++) {
                float4 w = wp[jj];
                aa += w.x * ha[4 * jj] + w.y * ha[4 * jj + 1] + w.z * ha[4 * jj + 2] + w.w * ha[4 * jj + 3];
                ab += w.x * hb[4 * jj] + w.y * hb[4 * jj + 1] + w.z * hb[4 * jj + 2] + w.w * hb[4 * jj + 3];
            }
            sa[q] = ((mba >> q) & 1) ? (aa - dba) : NEG_INF;
            sb[q] = ((mbb >> q) & 1) ? (ab - dbb) : NEG_INF;
        }

        // softmax over 256 LEDs: 2 values/thread, 4 warps
        #pragma unroll
        for (int q = 0; q < NRSS; q++) {
            float v = wredmax(fmaxf(sa[q], sb[q]));
            if (lane == 0) sm.red[q * 4 + wid] = v;
        }
        __syncthreads();
        if (tid < NRSS) {
            float v = sm.red[tid * 4];
            #pragma unroll
            for (int w = 1; w < 4; w++) v = fmaxf(v, sm.red[tid * 4 + w]);
            sm.bmax[tid] = v;
        }
        __syncthreads();
        #pragma unroll
        for (int q = 0; q < NRSS; q++) {
            float m = sm.bmax[q];
            float ea = __expf(sa[q] - m), eb = __expf(sb[q] - m);
            sa[q] = ea; sb[q] = eb;
            float v = wredsum(ea + eb);
            if (lane == 0) sm.red[q * 4 + wid] = v;
        }
        __syncthreads();
        if (tid < NRSS) {
            float v = 0.f;
            #pragma unroll
            for (int w = 0; w < 4; w++) v += sm.red[tid * 4 + w];
            sm.binv[tid] = 1.f / v;
        }
        __syncthreads();
        #pragma unroll
        for (int q = 0; q < NRSS; q++) {
            float inv = sm.binv[q];
            size_t base = ((size_t)b * NRSS + q) << 8;
            out[base + tid] = sa[q] * inv;
            out[base + tid + 128] = sb[q] * inv;
        }
        __syncthreads();  // protect smem scratch before next iteration
    }
}

extern "C" void kernel_launch(void* const* d_in, const int* in_sizes, int n_in,
                              void* d_out, int out_size) {
    (void)in_sizes; (void)n_in; (void)out_size;
    const float* rss_t  = (const float*)d_in[0];
    const float* led_f  = (const float*)d_in[1];
    const float* led_p  = (const float*)d_in[2];
    const float* prevp  = (const float*)d_in[3];
    const int*   fmask  = (const int*)  d_in[4];
    const float* lstm   = (const float*)d_in[5];
    const float* me_w1  = (const float*)d_in[6];
    const float* me_b1  = (const float*)d_in[7];
    const float* me_w2  = (const float*)d_in[8];
    const float* me_b2  = (const float*)d_in[9];
    const float* ci_w   = (const float*)d_in[10];
    const float* ci_b   = (const float*)d_in[11];
    const float* qf_w1  = (const float*)d_in[12];
    const float* qf_b1  = (const float*)d_in[13];
    const float* qf_w2  = (const float*)d_in[14];
    const float* qf_b2  = (const float*)d_in[15];
    const float* kp_w1  = (const float*)d_in[16];
    const float* kp_b1  = (const float*)d_in[17];
    const float* kp_w2  = (const float*)d_in[18];
    const float* kp_b2  = (const float*)d_in[19];
    const float* ss_w   = (const float*)d_in[20];
    const float* ss_b   = (const float*)d_in[21];
    float* out = (float*)d_out;

    static int smem_set = 0;
    if (!smem_set) {
        cudaFuncSetAttribute(cah_kernel, cudaFuncAttributeMaxDynamicSharedMemorySize,
                             (int)sizeof(SMem));
        smem_set = 1;
    }

    fold_kernel<<<8, 256>>>(qf_w2, qf_b2, kp_w2, kp_b2);
    cah_kernel<<<NBLK, NT, sizeof(SMem)>>>(rss_t, led_f, led_p, prevp, fmask, lstm,
                                           me_w1, me_b1, me_w2, me_b2, ci_w, ci_b,
                                           qf_w1, qf_b1, kp_w1, kp_b1, ss_w, ss_b, out);
}